// round 15
// baseline (speedup 1.0000x reference)
#include <cuda_runtime.h>
#include <math.h>

// S4 diagonal complex SSM, chunked formulation.
// R13: pass3 replaced by convolution + matvec form:
//   y_t = sum_{j<=t} K_d[t-j] x_j + M_d[t] . (h0re,h0im)
// K (64/d) and M (64x32/d) precomputed by s4_prep/s4_prep2 (parameter-only).
// s4_out: per (d,chunk): triangular 64-tap conv + 64x32 matvec — no scan,
// no serial chain, no shfl, no transcendentals. Thread owns t-block pair
// (I, 7-I) -> uniform 9 J-batches; warp = one I (uniform trips).
// pass1 (k=8 blocked scan, pipelined tiles) and pass2 unchanged from R12.

#define LL 4096
#define DD 1024
#define NN 16
#define CC 64       // chunks
#define TT 64       // timesteps per chunk
#define DW 16       // d-channels per pass1 block
#define PAD 68      // padded row stride for smem tiles
#define CB1 4       // chunks per pass1 block
#define DT3 8       // d-tile for s4_out
#define CT3 4       // c-tile for s4_out

__device__ float g_S_re[CC * DD * NN];
__device__ float g_S_im[CC * DD * NN];
__device__ float g_Kp [DD * TT * NN];   // partial K (pre-reduce over n)
__device__ float g_K  [DD * TT];        // K with D folded at tau=0
__device__ float g_Mre[DD * TT * NN];   // Re(c * lam^{t+1})
__device__ float g_Mim[DD * TT * NN];   // -Im(c * lam^{t+1})

// ---------------- packed f32x2 helpers (pass1) ----------------
struct f2 { unsigned long long v; };

__device__ __forceinline__ f2 f2pack(float lo, float hi) {
    f2 r; asm("mov.b64 %0, {%1, %2};" : "=l"(r.v) : "f"(lo), "f"(hi)); return r;
}
__device__ __forceinline__ void f2unpack(f2 a, float& lo, float& hi) {
    asm("mov.b64 {%0, %1}, %2;" : "=f"(lo), "=f"(hi) : "l"(a.v));
}
__device__ __forceinline__ f2 f2fma(f2 a, f2 b, f2 c) {
    f2 r; asm("fma.rn.f32x2 %0, %1, %2, %3;" : "=l"(r.v) : "l"(a.v), "l"(b.v), "l"(c.v)); return r;
}
__device__ __forceinline__ f2 f2mul(f2 a, f2 b) {
    f2 r; asm("mul.rn.f32x2 %0, %1, %2;" : "=l"(r.v) : "l"(a.v), "l"(b.v)); return r;
}
__device__ __forceinline__ f2 f2zero() { f2 r; r.v = 0ull; return r; }

__device__ __forceinline__ float softplus_f(float v) {
    return (v > 20.0f) ? v : log1pf(expf(v));
}
__device__ __forceinline__ void lam_dn(float dt, float ar, float ai,
                                       float& lre, float& lim) {
    float m = expf(dt * ar);
    float s, c;
    sincosf(dt * ai, &s, &c);
    lre = m * c;
    lim = m * s;
}

// ---------------- prep: per (d,n) evolve K partials and M rows --------------
__global__ void __launch_bounds__(128)
s4_prep(const float* __restrict__ Delta,
        const float* __restrict__ A_re, const float* __restrict__ A_im,
        const float* __restrict__ B_re, const float* __restrict__ B_im,
        const float* __restrict__ C_re, const float* __restrict__ C_im) {
    const int i = blockIdx.x * blockDim.x + threadIdx.x;   // d*NN + n
    const int d = i >> 4;
    const int n = i & 15;

    const float dt = softplus_f(Delta[d]);
    float lr, li;
    lam_dn(dt, A_re[i], A_im[i], lr, li);
    const float wr = dt * B_re[i], wi = dt * B_im[i];
    const float cr = C_re[i],      ci = C_im[i];

    // p = c*w  (K contribution at tau=0);  m = c*lam  (bias at t=0)
    float pr = cr * wr - ci * wi;
    float pi = cr * wi + ci * wr;
    float mr = cr * lr - ci * li;
    float mi = cr * li + ci * lr;

    #pragma unroll 4
    for (int t = 0; t < TT; t++) {
        const int idx = (d * TT + t) * NN + n;
        g_Kp [idx] = pr;
        g_Mre[idx] = mr;
        g_Mim[idx] = -mi;
        const float npr = lr * pr - li * pi;
        pi = lr * pi + li * pr;  pr = npr;
        const float nmr = lr * mr - li * mi;
        mi = lr * mi + li * mr;  mr = nmr;
    }
}

// ---------------- prep2: reduce K over n, fold D into K[0] ------------------
__global__ void __launch_bounds__(128)
s4_prep2(const float* __restrict__ D_param) {
    const int j = blockIdx.x * blockDim.x + threadIdx.x;   // d*TT + t
    const int d = j >> 6;
    const int t = j & 63;
    const float4* kp = (const float4*)&g_Kp[j * NN];
    float s = 0.0f;
    #pragma unroll
    for (int g = 0; g < 4; g++) {
        const float4 v = kp[g];
        s += v.x + v.y + v.z + v.w;
    }
    if (t == 0) s += D_param[d];
    g_K[j] = s;
}

// ---------------- pass 1: local chunk scans, k=8, pipelined tiles -----------
__global__ void __launch_bounds__(128, 8)
s4_pass1(const float* __restrict__ x, const float* __restrict__ Delta,
         const float* __restrict__ A_re, const float* __restrict__ A_im,
         const float* __restrict__ B_re, const float* __restrict__ B_im) {
    __shared__ float xs_sm[2][DW * PAD];
    const int tid = threadIdx.x;
    const int dl  = tid >> 3;
    const int o   = tid & 7;
    const int d   = blockIdx.x * DW + dl;
    const int nb  = o * 2;
    const int c0  = blockIdx.y * CB1;

    const int lt  = tid >> 2;
    const int ldq = (tid & 3) * 4;
    const float* xgb = x + blockIdx.x * DW;

    const float dt = softplus_f(Delta[d]);
    const float2 ar2 = *(const float2*)&A_re[d * NN + nb];
    const float2 ai2 = *(const float2*)&A_im[d * NN + nb];
    const float2 br2 = *(const float2*)&B_re[d * NN + nb];
    const float2 bi2 = *(const float2*)&B_im[d * NN + nb];
    const float arr[2] = {ar2.x, ar2.y};
    const float aii[2] = {ai2.x, ai2.y};
    const float brr[2] = {br2.x, br2.y};
    const float bii[2] = {bi2.x, bi2.y};

    float cr[8][2], ci[8][2], l8r[2], l8i[2];
    #pragma unroll
    for (int k = 0; k < 2; k++) {
        float lr, li;
        lam_dn(dt, arr[k], aii[k], lr, li);
        cr[0][k] = dt * brr[k];
        ci[0][k] = dt * bii[k];
        #pragma unroll
        for (int j = 1; j < 8; j++) {
            cr[j][k] = lr * cr[j-1][k] - li * ci[j-1][k];
            ci[j][k] = lr * ci[j-1][k] + li * cr[j-1][k];
        }
        float pr = lr, pi = li;
        #pragma unroll
        for (int s = 0; s < 3; s++) {
            const float nr = pr * pr - pi * pi;
            pi = 2.0f * pr * pi;
            pr = nr;
        }
        l8r[k] = pr; l8i[k] = pi;
    }

    f2 Cr[8], Ci[8];
    #pragma unroll
    for (int j = 0; j < 8; j++) {
        Cr[j] = f2pack(cr[j][0], cr[j][1]);
        Ci[j] = f2pack(ci[j][0], ci[j][1]);
    }
    const f2 L8re  = f2pack(l8r[0], l8r[1]);
    const f2 L8im  = f2pack(l8i[0], l8i[1]);
    const f2 nL8im = f2pack(-l8i[0], -l8i[1]);

    {
        const float* xg = xgb + (size_t)c0 * TT * DD;
        float4 v0 = *(const float4*)&xg[lt * DD + ldq];
        float4 v1 = *(const float4*)&xg[(lt + 32) * DD + ldq];
        float* b = xs_sm[0];
        b[(ldq + 0) * PAD + lt] = v0.x;  b[(ldq + 1) * PAD + lt] = v0.y;
        b[(ldq + 2) * PAD + lt] = v0.z;  b[(ldq + 3) * PAD + lt] = v0.w;
        b[(ldq + 0) * PAD + lt + 32] = v1.x;  b[(ldq + 1) * PAD + lt + 32] = v1.y;
        b[(ldq + 2) * PAD + lt + 32] = v1.z;  b[(ldq + 3) * PAD + lt + 32] = v1.w;
    }
    __syncthreads();

    #pragma unroll 1
    for (int u = 0; u < CB1; u++) {
        const int c   = c0 + u;
        const int cur = u & 1;
        const bool pre = (u + 1) < CB1;

        float4 p0, p1;
        if (pre) {
            const float* xg = xgb + (size_t)(c + 1) * TT * DD;
            p0 = *(const float4*)&xg[lt * DD + ldq];
            p1 = *(const float4*)&xg[(lt + 32) * DD + ldq];
        }

        const float* xr = &xs_sm[cur][dl * PAD];
        f2 hre = f2zero(), him = f2zero();
        #pragma unroll 2
        for (int t = 0; t < TT; t += 8) {
            const float4 xa = *(const float4*)&xr[t];
            const float4 xb = *(const float4*)&xr[t + 4];
            const f2 x1 = f2pack(xa.x, xa.x), x2 = f2pack(xa.y, xa.y);
            const f2 x3 = f2pack(xa.z, xa.z), x4 = f2pack(xa.w, xa.w);
            const f2 x5 = f2pack(xb.x, xb.x), x6 = f2pack(xb.y, xb.y);
            const f2 x7 = f2pack(xb.z, xb.z), x8 = f2pack(xb.w, xb.w);
            f2 tr = f2fma(Cr[1], x7, f2mul(Cr[0], x8));
            tr = f2fma(Cr[2], x6, tr);
            tr = f2fma(Cr[3], x5, tr);
            tr = f2fma(Cr[4], x4, tr);
            tr = f2fma(Cr[5], x3, tr);
            tr = f2fma(Cr[6], x2, tr);
            tr = f2fma(Cr[7], x1, tr);
            f2 ti = f2fma(Ci[1], x7, f2mul(Ci[0], x8));
            ti = f2fma(Ci[2], x6, ti);
            ti = f2fma(Ci[3], x5, ti);
            ti = f2fma(Ci[4], x4, ti);
            ti = f2fma(Ci[5], x3, ti);
            ti = f2fma(Ci[6], x2, ti);
            ti = f2fma(Ci[7], x1, ti);
            f2 nr = f2fma(L8re, hre, f2fma(nL8im, him, tr));
            f2 ni = f2fma(L8re, him, f2fma(L8im,  hre, ti));
            hre = nr; him = ni;
        }

        float r0, r1, i0, i1;
        f2unpack(hre, r0, r1);
        f2unpack(him, i0, i1);
        const int base = (c * DD + d) * NN + nb;
        *(float2*)&g_S_re[base] = make_float2(r0, r1);
        *(float2*)&g_S_im[base] = make_float2(i0, i1);

        if (pre) {
            float* b = xs_sm[1 - cur];
            b[(ldq + 0) * PAD + lt] = p0.x;  b[(ldq + 1) * PAD + lt] = p0.y;
            b[(ldq + 2) * PAD + lt] = p0.z;  b[(ldq + 3) * PAD + lt] = p0.w;
            b[(ldq + 0) * PAD + lt + 32] = p1.x;  b[(ldq + 1) * PAD + lt + 32] = p1.y;
            b[(ldq + 2) * PAD + lt + 32] = p1.z;  b[(ldq + 3) * PAD + lt + 32] = p1.w;
            __syncthreads();
        }
    }
}

// ---------------- pass 2: cross-chunk scan (ends -> inits, in place) --------
__global__ void __launch_bounds__(128)
s4_pass2(const float* __restrict__ Delta,
         const float* __restrict__ A_re, const float* __restrict__ A_im) {
    const int i = blockIdx.x * blockDim.x + threadIdx.x;  // i = d*NN + n
    const int d = i >> 4;

    const float dt = softplus_f(Delta[d]);
    float lr, li;
    lam_dn(dt, A_re[i], A_im[i], lr, li);
    #pragma unroll
    for (int s = 0; s < 6; s++) {   // Lam^64
        float nr = lr * lr - li * li;
        li = 2.0f * lr * li;
        lr = nr;
    }

    float er[8], ei[8];
    #pragma unroll
    for (int u = 0; u < 8; u++) {
        const int idx = u * (DD * NN) + i;
        er[u] = g_S_re[idx];
        ei[u] = g_S_im[idx];
    }

    float hr = 0.0f, hi = 0.0f;
    #pragma unroll 1
    for (int cb = 0; cb < CC; cb += 8) {
        const bool more = (cb + 8) < CC;
        float er2[8], ei2[8];
        #pragma unroll
        for (int u = 0; u < 8; u++) {
            const int idx = (cb + 8 + u) * (DD * NN) + i;
            er2[u] = more ? g_S_re[idx] : 0.0f;
            ei2[u] = more ? g_S_im[idx] : 0.0f;
        }
        #pragma unroll
        for (int u = 0; u < 8; u++) {
            const int idx = (cb + u) * (DD * NN) + i;
            g_S_re[idx] = hr;
            g_S_im[idx] = hi;
            const float tr = lr * hr - li * hi + er[u];
            hi = lr * hi + li * hr + ei[u];
            hr = tr;
        }
        #pragma unroll
        for (int u = 0; u < 8; u++) { er[u] = er2[u]; ei[u] = ei2[u]; }
    }
}

// ---------------- s4_out: conv + matvec output kernel -----------------------
// one thread computes y for (d, c, t-blocks I and 7-I).
__device__ __forceinline__ void out_block(
    int I, float (&ys)[8],
    const float* __restrict__ Mre_d, const float* __restrict__ Mim_d,
    const float (&h0r)[16], const float (&h0i)[16],
    const float* __restrict__ xrow, const float* __restrict__ Krow) {
    // bias: ys[i] = M[8I+i] . (h0re, h0im)
    #pragma unroll
    for (int i = 0; i < 8; i++) {
        const float4* mr = (const float4*)&Mre_d[(8 * I + i) * NN];
        const float4* mi = (const float4*)&Mim_d[(8 * I + i) * NN];
        float acc = 0.0f;
        #pragma unroll
        for (int g = 0; g < 4; g++) {
            const float4 r4 = __ldg(&mr[g]);
            const float4 i4 = __ldg(&mi[g]);
            acc += r4.x * h0r[4*g+0] + r4.y * h0r[4*g+1]
                 + r4.z * h0r[4*g+2] + r4.w * h0r[4*g+3];
            acc += i4.x * h0i[4*g+0] + i4.y * h0i[4*g+1]
                 + i4.z * h0i[4*g+2] + i4.w * h0i[4*g+3];
        }
        ys[i] = acc;
    }
    // conv: ys[i] += sum_j K[8I+i-j] x[j], K padded with zeros for tau<0
    for (int jb = 0; jb <= I; jb++) {          // uniform per warp (warp = one I)
        const int dj = I - jb;
        float Kw[15];
        #pragma unroll
        for (int k = 0; k < 15; k++)
            Kw[k] = Krow[8 * dj + k + 1];      // = K[8*dj + k - 7] (padded)
        const float4 xa = *(const float4*)&xrow[8 * jb];
        const float4 xb = *(const float4*)&xrow[8 * jb + 4];
        const float x8[8] = {xa.x, xa.y, xa.z, xa.w, xb.x, xb.y, xb.z, xb.w};
        #pragma unroll
        for (int i = 0; i < 8; i++) {
            #pragma unroll
            for (int j8 = 0; j8 < 8; j8++)
                ys[i] += Kw[i - j8 + 7] * x8[j8];
        }
    }
}

__global__ void __launch_bounds__(128, 6)
s4_out(const float* __restrict__ x, float* __restrict__ out) {
    __shared__ float xs[CT3 * DT3 * PAD];   // [cl*8+dl][j]
    __shared__ float Ks[DT3 * 72];          // [dl][tau+8], zeros for tau<0
    const int tid  = threadIdx.x;
    const int ip   = tid >> 5;              // 0..3 (warp id -> t-block pair)
    const int lane = tid & 31;
    const int dl   = lane >> 2;             // 0..7
    const int cl   = lane & 3;              // 0..3
    const int d0   = blockIdx.x * DT3;
    const int d    = d0 + dl;
    const int c    = blockIdx.y * CT3 + cl;

    // stage x tile transposed: xs[(cl*8+dl)][j]
    {
        const float* xg = x + (size_t)(blockIdx.y * CT3) * TT * DD + d0;
        #pragma unroll
        for (int r = 0; r < 4; r++) {
            const int slot  = tid + r * 128;      // 0..511 float4 slots
            const int rowid = slot >> 1;          // clr*TT + j
            const int half  = slot & 1;
            const int clr   = rowid >> 6;
            const int j     = rowid & 63;
            const float4 v  = *(const float4*)&xg[(clr * TT + j) * DD + half * 4];
            const int rb = clr * 8 + half * 4;
            xs[(rb + 0) * PAD + j] = v.x;
            xs[(rb + 1) * PAD + j] = v.y;
            xs[(rb + 2) * PAD + j] = v.z;
            xs[(rb + 3) * PAD + j] = v.w;
        }
    }
    // stage padded K rows
    for (int s = tid; s < DT3 * 72; s += 128) {
        const int dd  = s / 72;
        const int ti  = s % 72;
        const int tau = ti - 8;
        Ks[dd * 72 + ti] = (tau >= 0) ? g_K[(d0 + dd) * TT + tau] : 0.0f;
    }
    __syncthreads();

    // h0 for (d, c)
    float h0r[16], h0i[16];
    {
        const int sb = (c * DD + d) * NN;
        #pragma unroll
        for (int g = 0; g < 4; g++) {
            const float4 r4 = *(const float4*)&g_S_re[sb + 4 * g];
            const float4 i4 = *(const float4*)&g_S_im[sb + 4 * g];
            h0r[4*g+0] = r4.x; h0r[4*g+1] = r4.y; h0r[4*g+2] = r4.z; h0r[4*g+3] = r4.w;
            h0i[4*g+0] = i4.x; h0i[4*g+1] = i4.y; h0i[4*g+2] = i4.z; h0i[4*g+3] = i4.w;
        }
    }

    const float* Mre_d = &g_Mre[d * TT * NN];
    const float* Mim_d = &g_Mim[d * TT * NN];
    const float* xrow  = &xs[(cl * 8 + dl) * PAD];
    const float* Krow  = &Ks[dl * 72];
    float* og = out + (size_t)c * TT * DD + d;

    const int IA = ip;
    const int IB = 7 - ip;

    float ysA[8];
    out_block(IA, ysA, Mre_d, Mim_d, h0r, h0i, xrow, Krow);
    #pragma unroll
    for (int i = 0; i < 8; i++)
        og[(8 * IA + i) * DD] = ysA[i];

    float ysB[8];
    out_block(IB, ysB, Mre_d, Mim_d, h0r, h0i, xrow, Krow);
    #pragma unroll
    for (int i = 0; i < 8; i++)
        og[(8 * IB + i) * DD] = ysB[i];
}

extern "C" void kernel_launch(void* const* d_in, const int* in_sizes, int n_in,
                              void* d_out, int out_size) {
    const float* x     = (const float*)d_in[0];
    const float* Delta = (const float*)d_in[1];
    const float* A_re  = (const float*)d_in[2];
    const float* A_im  = (const float*)d_in[3];
    const float* B_re  = (const float*)d_in[4];
    const float* B_im  = (const float*)d_in[5];
    const float* C_re  = (const float*)d_in[6];
    const float* C_im  = (const float*)d_in[7];
    const float* Dp    = (const float*)d_in[8];
    float* out = (float*)d_out;

    dim3 blk(128);
    s4_prep <<<(DD * NN) / 128, blk>>>(Delta, A_re, A_im, B_re, B_im, C_re, C_im);
    s4_prep2<<<(DD * TT) / 128, blk>>>(Dp);
    s4_pass1<<<dim3(DD / DW, CC / CB1), blk>>>(x, Delta, A_re, A_im, B_re, B_im);
    s4_pass2<<<(DD * NN) / 128, blk>>>(Delta, A_re, A_im);
    s4_out  <<<dim3(DD / DT3, CC / CT3), blk>>>(x, out);
}

// round 17
// speedup vs baseline: 1.8402x; 1.8402x over previous
#include <cuda_runtime.h>
#include <math.h>

// S4 diagonal complex SSM scan, chunked 3-pass formulation.
// R15 = R14 resubmitted verbatim (previous round died to a container
//      provisioning failure; the kernel never ran).
//      pass1 = pipelined double-buffered tiles, k=8 step blocking (R9/R12).
//      pass2 = prefetch depth 16 (halves exposed-latency rounds; R13's ncu
//              window showed pass2 at ~10.7us, 6% occ — the hidden cost).
//      pass3 = R8 epilogue (4-way split, predicated q==0 stores, CB3=2).

#define LL 4096
#define DD 1024
#define NN 16
#define CC 64       // chunks
#define TT 64       // timesteps per chunk
#define DW 16       // d-channels per pass1 block (128 thr / 8 octs)
#define PAD 68      // padded row stride for smem x tiles
#define DW3 32      // d-channels per pass3 block (128 thr / 4 quarters)
#define CB1 4       // chunks per pass1 block
#define CB3 2       // chunks per pass3 block

__device__ float g_S_re[CC * DD * NN];
__device__ float g_S_im[CC * DD * NN];

// ---------------- packed f32x2 helpers ----------------
struct f2 { unsigned long long v; };

__device__ __forceinline__ f2 f2pack(float lo, float hi) {
    f2 r; asm("mov.b64 %0, {%1, %2};" : "=l"(r.v) : "f"(lo), "f"(hi)); return r;
}
__device__ __forceinline__ void f2unpack(f2 a, float& lo, float& hi) {
    asm("mov.b64 {%0, %1}, %2;" : "=f"(lo), "=f"(hi) : "l"(a.v));
}
__device__ __forceinline__ f2 f2fma(f2 a, f2 b, f2 c) {
    f2 r; asm("fma.rn.f32x2 %0, %1, %2, %3;" : "=l"(r.v) : "l"(a.v), "l"(b.v), "l"(c.v)); return r;
}
__device__ __forceinline__ f2 f2mul(f2 a, f2 b) {
    f2 r; asm("mul.rn.f32x2 %0, %1, %2;" : "=l"(r.v) : "l"(a.v), "l"(b.v)); return r;
}
__device__ __forceinline__ f2 f2add(f2 a, f2 b) {
    f2 r; asm("add.rn.f32x2 %0, %1, %2;" : "=l"(r.v) : "l"(a.v), "l"(b.v)); return r;
}
__device__ __forceinline__ f2 f2zero() { f2 r; r.v = 0ull; return r; }

__device__ __forceinline__ float softplus_f(float v) {
    return (v > 20.0f) ? v : log1pf(expf(v));
}

__device__ __forceinline__ void lam_dn(float dt, float ar, float ai,
                                       float& lre, float& lim) {
    float m = expf(dt * ar);
    float s, c;
    sincosf(dt * ai, &s, &c);
    lre = m * c;
    lim = m * s;
}

// ---------------- pass 1: local chunk scans, k=8, pipelined tiles -----------
__global__ void __launch_bounds__(128, 8)
s4_pass1(const float* __restrict__ x, const float* __restrict__ Delta,
         const float* __restrict__ A_re, const float* __restrict__ A_im,
         const float* __restrict__ B_re, const float* __restrict__ B_im) {
    __shared__ float xs_sm[2][DW * PAD];
    const int tid = threadIdx.x;
    const int dl  = tid >> 3;          // 0..15
    const int o   = tid & 7;           // oct -> 2 states
    const int d   = blockIdx.x * DW + dl;
    const int nb  = o * 2;
    const int c0  = blockIdx.y * CB1;

    // tile-load lane mapping: two float4 slots per thread
    const int lt  = tid >> 2;          // 0..31  (t for slot 0; slot 1 = +32)
    const int ldq = (tid & 3) * 4;     // 0,4,8,12
    const float* xgb = x + blockIdx.x * DW;

    // ---- one-time coefficient setup ----
    const float dt = softplus_f(Delta[d]);
    const float2 ar2 = *(const float2*)&A_re[d * NN + nb];
    const float2 ai2 = *(const float2*)&A_im[d * NN + nb];
    const float2 br2 = *(const float2*)&B_re[d * NN + nb];
    const float2 bi2 = *(const float2*)&B_im[d * NN + nb];
    const float arr[2] = {ar2.x, ar2.y};
    const float aii[2] = {ai2.x, ai2.y};
    const float brr[2] = {br2.x, br2.y};
    const float bii[2] = {bi2.x, bi2.y};

    float cr[8][2], ci[8][2], l8r[2], l8i[2];
    #pragma unroll
    for (int k = 0; k < 2; k++) {
        float lr, li;
        lam_dn(dt, arr[k], aii[k], lr, li);
        cr[0][k] = dt * brr[k];
        ci[0][k] = dt * bii[k];
        #pragma unroll
        for (int j = 1; j < 8; j++) {
            cr[j][k] = lr * cr[j-1][k] - li * ci[j-1][k];
            ci[j][k] = lr * ci[j-1][k] + li * cr[j-1][k];
        }
        float pr = lr, pi = li;
        #pragma unroll
        for (int s = 0; s < 3; s++) {
            const float nr = pr * pr - pi * pi;
            pi = 2.0f * pr * pi;
            pr = nr;
        }
        l8r[k] = pr; l8i[k] = pi;
    }

    f2 Cr[8], Ci[8];
    #pragma unroll
    for (int j = 0; j < 8; j++) {
        Cr[j] = f2pack(cr[j][0], cr[j][1]);
        Ci[j] = f2pack(ci[j][0], ci[j][1]);
    }
    const f2 L8re  = f2pack(l8r[0], l8r[1]);
    const f2 L8im  = f2pack(l8i[0], l8i[1]);
    const f2 nL8im = f2pack(-l8i[0], -l8i[1]);

    // ---- prologue: load chunk c0 into buffer 0 ----
    {
        const float* xg = xgb + (size_t)c0 * TT * DD;
        float4 v0 = *(const float4*)&xg[lt * DD + ldq];
        float4 v1 = *(const float4*)&xg[(lt + 32) * DD + ldq];
        float* b = xs_sm[0];
        b[(ldq + 0) * PAD + lt] = v0.x;  b[(ldq + 1) * PAD + lt] = v0.y;
        b[(ldq + 2) * PAD + lt] = v0.z;  b[(ldq + 3) * PAD + lt] = v0.w;
        b[(ldq + 0) * PAD + lt + 32] = v1.x;  b[(ldq + 1) * PAD + lt + 32] = v1.y;
        b[(ldq + 2) * PAD + lt + 32] = v1.z;  b[(ldq + 3) * PAD + lt + 32] = v1.w;
    }
    __syncthreads();

    #pragma unroll 1
    for (int u = 0; u < CB1; u++) {
        const int c   = c0 + u;
        const int cur = u & 1;
        const bool pre = (u + 1) < CB1;

        // issue next tile's loads NOW (results consumed after compute)
        float4 p0, p1;
        if (pre) {
            const float* xg = xgb + (size_t)(c + 1) * TT * DD;
            p0 = *(const float4*)&xg[lt * DD + ldq];
            p1 = *(const float4*)&xg[(lt + 32) * DD + ldq];
        }

        // ---- compute chunk c from buffer cur ----
        const float* xr = &xs_sm[cur][dl * PAD];
        f2 hre = f2zero(), him = f2zero();
        #pragma unroll 2
        for (int t = 0; t < TT; t += 8) {
            const float4 xa = *(const float4*)&xr[t];
            const float4 xb = *(const float4*)&xr[t + 4];
            const f2 x1 = f2pack(xa.x, xa.x), x2 = f2pack(xa.y, xa.y);
            const f2 x3 = f2pack(xa.z, xa.z), x4 = f2pack(xa.w, xa.w);
            const f2 x5 = f2pack(xb.x, xb.x), x6 = f2pack(xb.y, xb.y);
            const f2 x7 = f2pack(xb.z, xb.z), x8 = f2pack(xb.w, xb.w);
            f2 tr = f2fma(Cr[1], x7, f2mul(Cr[0], x8));
            tr = f2fma(Cr[2], x6, tr);
            tr = f2fma(Cr[3], x5, tr);
            tr = f2fma(Cr[4], x4, tr);
            tr = f2fma(Cr[5], x3, tr);
            tr = f2fma(Cr[6], x2, tr);
            tr = f2fma(Cr[7], x1, tr);
            f2 ti = f2fma(Ci[1], x7, f2mul(Ci[0], x8));
            ti = f2fma(Ci[2], x6, ti);
            ti = f2fma(Ci[3], x5, ti);
            ti = f2fma(Ci[4], x4, ti);
            ti = f2fma(Ci[5], x3, ti);
            ti = f2fma(Ci[6], x2, ti);
            ti = f2fma(Ci[7], x1, ti);
            f2 nr = f2fma(L8re, hre, f2fma(nL8im, him, tr));
            f2 ni = f2fma(L8re, him, f2fma(L8im,  hre, ti));
            hre = nr; him = ni;
        }

        float r0, r1, i0, i1;
        f2unpack(hre, r0, r1);
        f2unpack(him, i0, i1);
        const int base = (c * DD + d) * NN + nb;
        *(float2*)&g_S_re[base] = make_float2(r0, r1);
        *(float2*)&g_S_im[base] = make_float2(i0, i1);

        // stage next tile and sync
        if (pre) {
            float* b = xs_sm[1 - cur];
            b[(ldq + 0) * PAD + lt] = p0.x;  b[(ldq + 1) * PAD + lt] = p0.y;
            b[(ldq + 2) * PAD + lt] = p0.z;  b[(ldq + 3) * PAD + lt] = p0.w;
            b[(ldq + 0) * PAD + lt + 32] = p1.x;  b[(ldq + 1) * PAD + lt + 32] = p1.y;
            b[(ldq + 2) * PAD + lt + 32] = p1.z;  b[(ldq + 3) * PAD + lt + 32] = p1.w;
            __syncthreads();
        }
    }
}

// ---------------- pass 2: cross-chunk scan, prefetch depth 16 ---------------
__global__ void __launch_bounds__(128)
s4_pass2(const float* __restrict__ Delta,
         const float* __restrict__ A_re, const float* __restrict__ A_im) {
    const int i = blockIdx.x * blockDim.x + threadIdx.x;  // i = d*NN + n
    const int d = i >> 4;

    const float dt = softplus_f(Delta[d]);
    float lr, li;
    lam_dn(dt, A_re[i], A_im[i], lr, li);
    #pragma unroll
    for (int s = 0; s < 6; s++) {   // Lam^64
        float nr = lr * lr - li * li;
        li = 2.0f * lr * li;
        lr = nr;
    }

    float er[16], ei[16];
    #pragma unroll
    for (int u = 0; u < 16; u++) {
        const int idx = u * (DD * NN) + i;
        er[u] = g_S_re[idx];
        ei[u] = g_S_im[idx];
    }

    float hr = 0.0f, hi = 0.0f;
    #pragma unroll 1
    for (int cb = 0; cb < CC; cb += 16) {
        const bool more = (cb + 16) < CC;
        float er2[16], ei2[16];
        #pragma unroll
        for (int u = 0; u < 16; u++) {
            const int idx = (cb + 16 + u) * (DD * NN) + i;
            er2[u] = more ? g_S_re[idx] : 0.0f;
            ei2[u] = more ? g_S_im[idx] : 0.0f;
        }
        #pragma unroll
        for (int u = 0; u < 16; u++) {
            const int idx = (cb + u) * (DD * NN) + i;
            g_S_re[idx] = hr;
            g_S_im[idx] = hi;
            const float tr = lr * hr - li * hi + er[u];
            hi = lr * hi + li * hr + ei[u];
            hr = tr;
        }
        #pragma unroll
        for (int u = 0; u < 16; u++) { er[u] = er2[u]; ei[u] = ei2[u]; }
    }
}

// ---------------- pass 3: full scan, 4-way split, 2 chunks/block ------------
__global__ void __launch_bounds__(128, 8)
s4_pass3(const float* __restrict__ x, const float* __restrict__ Delta,
         const float* __restrict__ A_re, const float* __restrict__ A_im,
         const float* __restrict__ B_re, const float* __restrict__ B_im,
         const float* __restrict__ C_re, const float* __restrict__ C_im,
         const float* __restrict__ D_param, float* __restrict__ out) {
    __shared__ float xs_sm[DW3 * PAD];
    const int tid = threadIdx.x;
    const int dl  = tid >> 2;          // 0..31
    const int q   = tid & 3;
    const int d   = blockIdx.x * DW3 + dl;
    const int nb  = q * 4;
    const int c0  = blockIdx.y * CB3;

    // ---- one-time setup (amortized over CB3 chunks) ----
    const float dt = softplus_f(Delta[d]);
    const float Dp = D_param[d];

    const float4 ar4 = *(const float4*)&A_re[d * NN + nb];
    const float4 ai4 = *(const float4*)&A_im[d * NN + nb];
    const float4 br4 = *(const float4*)&B_re[d * NN + nb];
    const float4 bi4 = *(const float4*)&B_im[d * NN + nb];
    const float4 cr4 = *(const float4*)&C_re[d * NN + nb];
    const float4 ci4 = *(const float4*)&C_im[d * NN + nb];

    const float arr[4] = {ar4.x, ar4.y, ar4.z, ar4.w};
    const float aii[4] = {ai4.x, ai4.y, ai4.z, ai4.w};
    const float brr[4] = {br4.x, br4.y, br4.z, br4.w};
    const float bii[4] = {bi4.x, bi4.y, bi4.z, bi4.w};
    const float crr[4] = {cr4.x, cr4.y, cr4.z, cr4.w};
    const float cii[4] = {ci4.x, ci4.y, ci4.z, ci4.w};

    float lr[4], li[4], vr[4], vi[4];
    #pragma unroll
    for (int k = 0; k < 4; k++) {
        lam_dn(dt, arr[k], aii[k], lr[k], li[k]);
        const float br = dt * brr[k], bi = dt * bii[k];
        vr[k] = crr[k] * br - cii[k] * bi;
        vi[k] = crr[k] * bi + cii[k] * br;
    }

    f2 lre[2], lim[2], nlim[2], wre[2], wim[2];
    lre[0]  = f2pack(lr[0], lr[1]);   lre[1]  = f2pack(lr[2], lr[3]);
    lim[0]  = f2pack(li[0], li[1]);   lim[1]  = f2pack(li[2], li[3]);
    nlim[0] = f2pack(-li[0], -li[1]); nlim[1] = f2pack(-li[2], -li[3]);
    wre[0]  = f2pack(vr[0], vr[1]);   wre[1]  = f2pack(vr[2], vr[3]);
    wim[0]  = f2pack(vi[0], vi[1]);   wim[1]  = f2pack(vi[2], vi[3]);

    const float* xr = &xs_sm[dl * PAD];

    #pragma unroll 1
    for (int u = 0; u < CB3; u++) {
        const int c = c0 + u;
        __syncthreads();
        // coalesced transposed x tile load: xs_sm[d][t] (32 d x 64 t)
        {
            const float* xg = x + (size_t)c * TT * DD + blockIdx.x * DW3;
            #pragma unroll
            for (int r = 0; r < 4; r++) {
                const int idx = tid + r * 128;     // 0..511 float4 slots
                const int t  = idx >> 3;           // 0..63
                const int dq = (idx & 7) * 4;      // 0,4,..,28
                float4 v = *(const float4*)&xg[t * DD + dq];
                xs_sm[(dq + 0) * PAD + t] = v.x;
                xs_sm[(dq + 1) * PAD + t] = v.y;
                xs_sm[(dq + 2) * PAD + t] = v.z;
                xs_sm[(dq + 3) * PAD + t] = v.w;
            }
        }
        __syncthreads();

        // per-chunk init state, C folded in: g = C (.) h
        const int base = (c * DD + d) * NN + nb;
        const float4 h0r4 = *(const float4*)&g_S_re[base];
        const float4 h0i4 = *(const float4*)&g_S_im[base];
        const float hrr[4] = {h0r4.x, h0r4.y, h0r4.z, h0r4.w};
        const float hii[4] = {h0i4.x, h0i4.y, h0i4.z, h0i4.w};
        float gr[4], gi[4];
        #pragma unroll
        for (int k = 0; k < 4; k++) {
            gr[k] = crr[k] * hrr[k] - cii[k] * hii[k];
            gi[k] = crr[k] * hii[k] + cii[k] * hrr[k];
        }
        f2 gre[2], gim[2];
        gre[0] = f2pack(gr[0], gr[1]); gre[1] = f2pack(gr[2], gr[3]);
        gim[0] = f2pack(gi[0], gi[1]); gim[1] = f2pack(gi[2], gi[3]);

        float* op = out + (size_t)c * TT * DD + d;

        #pragma unroll 1
        for (int tb = 0; tb < TT; tb += 8) {
            const float4 xa = *(const float4*)&xr[tb];
            const float4 xb = *(const float4*)&xr[tb + 4];
            const float xs[8] = {xa.x, xa.y, xa.z, xa.w, xb.x, xb.y, xb.z, xb.w};
            float ys[8];
            #pragma unroll
            for (int w = 0; w < 8; w++) {
                f2 x2 = f2pack(xs[w], xs[w]);
                #pragma unroll
                for (int j = 0; j < 2; j++) {
                    f2 nr = f2fma(lre[j], gre[j], f2fma(nlim[j], gim[j], f2mul(wre[j], x2)));
                    f2 ni = f2fma(lre[j], gim[j], f2fma(lim[j],  gre[j], f2mul(wim[j], x2)));
                    gre[j] = nr; gim[j] = ni;
                }
                f2 s = f2add(gre[0], gre[1]);
                float lo, hi;
                f2unpack(s, lo, hi);
                ys[w] = lo + hi;
            }
            #pragma unroll
            for (int w = 0; w < 8; w++)
                ys[w] += __shfl_xor_sync(0xFFFFFFFFu, ys[w], 1);
            #pragma unroll
            for (int w = 0; w < 8; w++)
                ys[w] += __shfl_xor_sync(0xFFFFFFFFu, ys[w], 2);
            if (q == 0) {
                #pragma unroll
                for (int w = 0; w < 8; w++)
                    op[(tb + w) * DD] = ys[w] + Dp * xs[w];
            }
        }
    }
}

extern "C" void kernel_launch(void* const* d_in, const int* in_sizes, int n_in,
                              void* d_out, int out_size) {
    const float* x     = (const float*)d_in[0];
    const float* Delta = (const float*)d_in[1];
    const float* A_re  = (const float*)d_in[2];
    const float* A_im  = (const float*)d_in[3];
    const float* B_re  = (const float*)d_in[4];
    const float* B_im  = (const float*)d_in[5];
    const float* C_re  = (const float*)d_in[6];
    const float* C_im  = (const float*)d_in[7];
    const float* Dp    = (const float*)d_in[8];
    float* out = (float*)d_out;

    dim3 blk(128);
    s4_pass1<<<dim3(DD / DW,  CC / CB1), blk>>>(x, Delta, A_re, A_im, B_re, B_im);
    s4_pass2<<<(DD * NN) / 128, blk>>>(Delta, A_re, A_im);
    s4_pass3<<<dim3(DD / DW3, CC / CB3), blk>>>(x, Delta, A_re, A_im, B_re, B_im,
                                                C_re, C_im, Dp, out);
}